// round 12
// baseline (speedup 1.0000x reference)
#include <cuda_runtime.h>
#include <cuda_bf16.h>

// Problem constants (SpectralClassifier: B=1024, S=128, D=768)
#define BB 1024
#define SS 128
#define DD 768
#define H1 256
#define H2 64
#define OUTC 2
#define ROWS 8
#define QTRS 4
#define DET_WORDS 256     // per-block detection sample (1KB, L2-broadcast)
#define SLICES 6          // k-slices per tile in gemm1
#define KSL (DD / SLICES) // 128 k per slice
#define KGRPS 4           // kgroups per gemm1 block
#define KPER (KSL / KGRPS)// 32 k per thread
#define KCH 4             // k-steps per register chunk
#define NCH (KPER / KCH)  // 8 chunks

// Scratch (no cudaMalloc allowed).
__device__ float g_vp[QTRS * BB * DD];    // unscaled partial sums [quarter][b][d]
__device__ float g_h1p[SLICES * BB * H1]; // gemm1 raw partials [slice][b][col]

// packed dual-fp32 FMA (sm_100+)
#define FMA_F32X2(d, a, b, c) \
    asm("fma.rn.f32x2 %0, %1, %2, %3;" : "=l"(d) : "l"(a), "l"(b), "l"(c))

__device__ __forceinline__ void cpasync16(float* smem_dst, const float* gsrc) {
    unsigned saddr = (unsigned)__cvta_generic_to_shared(smem_dst);
    asm volatile("cp.async.cg.shared.global [%0], [%1], 16;" :: "r"(saddr), "l"(gsrc) : "memory");
}
#define CP_COMMIT()  asm volatile("cp.async.commit_group;" ::: "memory")
#define CP_WAIT(n)   asm volatile("cp.async.wait_group %0;" :: "n"(n) : "memory")

__device__ __forceinline__ bool mask_at(const void* mask, int idx, int mode) {
    if (mode == 0) return ((const int*)mask)[idx] != 0;
    if (mode == 1) return ((const float*)mask)[idx] != 0.0f;
    return ((const unsigned char*)mask)[idx] != 0;
}

// ---------------------------------------------------------------------------
// Kernel A: partial masked seq-sums with inline mask-dtype detection.
// 4096 blocks: blockIdx.x = b*4 + q. (At ~65% HBM = achievable floor.)
// ---------------------------------------------------------------------------
__global__ void __launch_bounds__(192) reduce_kernel(
    const float* __restrict__ hidden, const void* __restrict__ mask)
{
    __shared__ int s_idx[32];
    __shared__ int s_cnt;
    __shared__ int s_mode;

    const int b   = blockIdx.x >> 2;
    const int q   = blockIdx.x & 3;
    const int lo  = (q == 0) ? 1 : (q * 32);
    const int nrows = (q == 0) ? 31 : 32;
    const int tid = threadIdx.x;

    {
        int bad_i = 0, bad_f = 0;
        const uint4* w4 = (const uint4*)mask;
        for (int i = tid; i < DET_WORDS / 4; i += 192) {
            uint4 v = __ldg(&w4[i]);
            unsigned arr[4] = {v.x, v.y, v.z, v.w};
            #pragma unroll
            for (int j = 0; j < 4; j++) {
                unsigned u = arr[j];
                if (u > 1u) bad_i = 1;
                float f = __uint_as_float(u);
                if (!(f == 0.0f || f == 1.0f)) bad_f = 1;
            }
        }
        bad_i = __any_sync(0xffffffffu, bad_i);
        bad_f = __any_sync(0xffffffffu, bad_f);
        if (tid == 0) s_mode = 0;
        __syncthreads();
        if ((tid & 31) == 0) {
            int mode = (!bad_i) ? 0 : ((!bad_f) ? 1 : 2);
            atomicMax(&s_mode, mode);
        }
        __syncthreads();
    }
    const int mode = s_mode;

    if (tid < 32) {
        bool m = (tid < nrows) && mask_at(mask, b * SS + lo + tid, mode);
        unsigned bal = __ballot_sync(0xffffffffu, m);
        if (m) s_idx[__popc(bal & ((1u << tid) - 1u))] = lo + tid;
        if (tid == 0) s_cnt = __popc(bal);
    }
    __syncthreads();

    const int cnt = s_cnt;
    const float4* hp = (const float4*)(hidden + (size_t)b * SS * DD);

    float4 a0 = make_float4(0.f, 0.f, 0.f, 0.f);
    float4 a1 = make_float4(0.f, 0.f, 0.f, 0.f);
    float4 a2 = make_float4(0.f, 0.f, 0.f, 0.f);
    float4 a3 = make_float4(0.f, 0.f, 0.f, 0.f);

    int i = 0;
    for (; i + 8 <= cnt; i += 8) {
        float4 x[8];
        #pragma unroll
        for (int u = 0; u < 8; u++)
            x[u] = __ldcs(&hp[s_idx[i + u] * (DD / 4) + tid]);
        a0.x += x[0].x; a0.y += x[0].y; a0.z += x[0].z; a0.w += x[0].w;
        a1.x += x[1].x; a1.y += x[1].y; a1.z += x[1].z; a1.w += x[1].w;
        a2.x += x[2].x; a2.y += x[2].y; a2.z += x[2].z; a2.w += x[2].w;
        a3.x += x[3].x; a3.y += x[3].y; a3.z += x[3].z; a3.w += x[3].w;
        a0.x += x[4].x; a0.y += x[4].y; a0.z += x[4].z; a0.w += x[4].w;
        a1.x += x[5].x; a1.y += x[5].y; a1.z += x[5].z; a1.w += x[5].w;
        a2.x += x[6].x; a2.y += x[6].y; a2.z += x[6].z; a2.w += x[6].w;
        a3.x += x[7].x; a3.y += x[7].y; a3.z += x[7].z; a3.w += x[7].w;
    }
    for (; i < cnt; i++) {
        float4 x0 = __ldcs(&hp[s_idx[i] * (DD / 4) + tid]);
        a0.x += x0.x; a0.y += x0.y; a0.z += x0.z; a0.w += x0.w;
    }

    float4 r;
    r.x = (a0.x + a1.x) + (a2.x + a3.x);
    r.y = (a0.y + a1.y) + (a2.y + a3.y);
    r.z = (a0.z + a1.z) + (a2.z + a3.z);
    r.w = (a0.w + a1.w) + (a2.w + a3.w);
    ((float4*)(g_vp + (size_t)(q * BB + b) * DD))[tid] = r;
}

// ---------------------------------------------------------------------------
// Kernel B: GEMM1 partials. Grid 768 = 128 tiles x 6 k-slices (tile-major:
// bid/6 = tile, bid%6 = slice). 512 threads = 4 kgroups x 128 col-pairs.
// Thread: 2 cols x 8 rows x 32 k (KCH=4 ping-pong LDG.64). 2 blocks/SM.
// Raw partials (no bias) -> g_h1p[slice].
// Dynamic smem (floats): vs 6144 | h1p 4*2048 = 8192 -> 14336 (57.3KB)
// ---------------------------------------------------------------------------
#define G1_SMEM 14336
#define OFF_G1_VS  0
#define OFF_G1_HP  6144

// one k-step: w2v = float2 weights for 2 cols; vkp -> vs[k][0]
#define KSTEP2(w2v, vkp) do {                                             \
    unsigned long long w0, w1;                                            \
    asm("mov.b64 %0, {%1, %1};" : "=l"(w0) : "f"((w2v).x));               \
    asm("mov.b64 %0, {%1, %1};" : "=l"(w1) : "f"((w2v).y));               \
    const ulonglong2 va = *(const ulonglong2*)(vkp);                      \
    const ulonglong2 vb = *(const ulonglong2*)((vkp) + 4);                \
    FMA_F32X2(accp[0], va.x, w0, accp[0]);                                \
    FMA_F32X2(accp[1], va.y, w0, accp[1]);                                \
    FMA_F32X2(accp[2], vb.x, w0, accp[2]);                                \
    FMA_F32X2(accp[3], vb.y, w0, accp[3]);                                \
    FMA_F32X2(accp[4], va.x, w1, accp[4]);                                \
    FMA_F32X2(accp[5], va.y, w1, accp[5]);                                \
    FMA_F32X2(accp[6], vb.x, w1, accp[6]);                                \
    FMA_F32X2(accp[7], vb.y, w1, accp[7]);                                \
} while (0)

__global__ void __launch_bounds__(512, 2) gemm1_kernel(const float* __restrict__ W1)
{
    extern __shared__ float smf[];
    float* vs  = smf + OFF_G1_VS;
    float* h1p = smf + OFF_G1_HP;

    const int tid   = threadIdx.x;
    const int c     = tid & 127;          // col pair: cols 2c, 2c+1
    const int kg    = tid >> 7;           // 0..3
    const int tile  = blockIdx.x / SLICES;
    const int slice = blockIdx.x % SLICES;
    const int r0    = tile * ROWS;
    const float inv127 = 1.0f / 127.0f;

    // --- Stage v rows: v = (sum of 4 quarter partials)/127, layout [k][r] ---
    #pragma unroll
    for (int ii = 0; ii < 3; ii++) {
        int idx = ii * 512 + tid;          // 0..1535 = 8 rows x 192 float4
        int r  = idx / (DD / 4);
        int c4 = idx % (DD / 4);
        const float4* p0 = (const float4*)(g_vp + (size_t)(0 * BB + r0 + r) * DD);
        const float4* p1 = (const float4*)(g_vp + (size_t)(1 * BB + r0 + r) * DD);
        const float4* p2 = (const float4*)(g_vp + (size_t)(2 * BB + r0 + r) * DD);
        const float4* p3 = (const float4*)(g_vp + (size_t)(3 * BB + r0 + r) * DD);
        float4 u0 = __ldg(&p0[c4]);
        float4 u1 = __ldg(&p1[c4]);
        float4 u2 = __ldg(&p2[c4]);
        float4 u3 = __ldg(&p3[c4]);
        float* dst = &vs[(c4 * 4) * ROWS + r];
        dst[0 * ROWS] = ((u0.x + u1.x) + (u2.x + u3.x)) * inv127;
        dst[1 * ROWS] = ((u0.y + u1.y) + (u2.y + u3.y)) * inv127;
        dst[2 * ROWS] = ((u0.z + u1.z) + (u2.z + u3.z)) * inv127;
        dst[3 * ROWS] = ((u0.w + u1.w) + (u2.w + u3.w)) * inv127;
    }
    __syncthreads();

    // --- Mainloop: 32 k = 8 chunks of 4, ping-pong, zero barriers ---
    unsigned long long accp[8];
    #pragma unroll
    for (int j = 0; j < 8; j++) accp[j] = 0ull;

    const int k0 = slice * KSL + kg * KPER;
    const float2* wp = (const float2*)W1 + (size_t)k0 * (H1 / 2) + c;
    const float*  vg = &vs[k0 * ROWS];

    float2 wA[KCH], wB[KCH];
    #pragma unroll
    for (int u = 0; u < KCH; u++)
        wA[u] = __ldg(wp + u * (H1 / 2));
    wp += KCH * (H1 / 2);

    #pragma unroll 1
    for (int it = 0; it < NCH / 2; it++) {
        #pragma unroll
        for (int u = 0; u < KCH; u++)
            wB[u] = __ldg(wp + u * (H1 / 2));
        wp += KCH * (H1 / 2);
        {
            const float* vk = vg + (it * 2 * KCH) * ROWS;
            #pragma unroll
            for (int u = 0; u < KCH; u++)
                KSTEP2(wA[u], vk + u * ROWS);
        }
        if (it < NCH / 2 - 1) {
            #pragma unroll
            for (int u = 0; u < KCH; u++)
                wA[u] = __ldg(wp + u * (H1 / 2));
            wp += KCH * (H1 / 2);
        }
        {
            const float* vk = vg + (it * 2 * KCH + KCH) * ROWS;
            #pragma unroll
            for (int u = 0; u < KCH; u++)
                KSTEP2(wB[u], vk + u * ROWS);
        }
    }

    // --- Write 4 kgroup partials: h1p[kg][row*256 + 2c + {0,1}] ---
    __syncthreads();
    {
        float* hp = h1p + kg * (ROWS * H1);
        #pragma unroll
        for (int j = 0; j < 4; j++) {
            float lo0, hi0, lo1, hi1;
            asm("mov.b64 {%0, %1}, %2;" : "=f"(lo0), "=f"(hi0) : "l"(accp[j]));
            asm("mov.b64 {%0, %1}, %2;" : "=f"(lo1), "=f"(hi1) : "l"(accp[4 + j]));
            *(float2*)&hp[(2 * j) * H1 + 2 * c]     = make_float2(lo0, lo1);
            *(float2*)&hp[(2 * j + 1) * H1 + 2 * c] = make_float2(hi0, hi1);
        }
    }
    __syncthreads();

    // --- Reduce 4 kgroup partials -> g_h1p[slice] (raw, no bias) ---
    {
        const int idx = tid * 4;           // 0..2044
        float4 s = *(const float4*)&h1p[idx];
        #pragma unroll
        for (int g = 1; g < KGRPS; g++) {
            float4 p = *(const float4*)&h1p[g * (ROWS * H1) + idx];
            s.x += p.x; s.y += p.y; s.z += p.z; s.w += p.w;
        }
        *(float4*)&g_h1p[(size_t)slice * BB * H1 + (size_t)r0 * H1 + idx] = s;
    }
}

// ---------------------------------------------------------------------------
// Kernel C: slice-sum + bias/relu + GEMM2 + GEMM3. Grid 128 x 512 threads.
// Dynamic smem (floats): sW2 16384 | h1s 2048 | h2s 512 -> 18944 (75.8KB)
// ---------------------------------------------------------------------------
#define G2_SMEM 18944
#define OFF_G2_W2  0
#define OFF_G2_H1  16384
#define OFF_G2_H2  18432

__global__ void __launch_bounds__(512) gemm23_kernel(
    const float* __restrict__ b1,
    const float* __restrict__ W2, const float* __restrict__ b2,
    const float* __restrict__ W3, const float* __restrict__ b3,
    float* __restrict__ out)
{
    extern __shared__ float smf[];
    float* sW2 = smf + OFF_G2_W2;
    float* h1s = smf + OFF_G2_H1;
    float* h2s = smf + OFF_G2_H2;

    const int tid = threadIdx.x;
    const int r0  = blockIdx.x * ROWS;

    // stage W2 via cp.async (overlaps the slice-sum below)
    #pragma unroll
    for (int i = 0; i < H1 * H2 / 4; i += 512)
        cpasync16(&sW2[(i + tid) * 4], &W2[(i + tid) * 4]);
    CP_COMMIT();

    // h1 = relu(sum of 6 slice partials + b1)
    {
        const int idx = tid * 4;           // 0..2044, col = idx & 255
        float4 s = make_float4(0.f, 0.f, 0.f, 0.f);
        #pragma unroll
        for (int sl = 0; sl < SLICES; sl++) {
            float4 p = __ldg((const float4*)(g_h1p + (size_t)sl * BB * H1
                                             + (size_t)r0 * H1) + tid);
            s.x += p.x; s.y += p.y; s.z += p.z; s.w += p.w;
        }
        float4 bb = *(const float4*)&b1[idx & (H1 - 1)];
        s.x = fmaxf(s.x + bb.x, 0.0f);
        s.y = fmaxf(s.y + bb.y, 0.0f);
        s.z = fmaxf(s.z + bb.z, 0.0f);
        s.w = fmaxf(s.w + bb.w, 0.0f);
        *(float4*)&h1s[idx] = s;
    }
    CP_WAIT(0);
    __syncthreads();

    // GEMM2: thread (r = tid>>6, j = tid&63)
    {
        const int j = tid & (H2 - 1);
        const int r = tid >> 6;
        float s0 = 0.0f;
        #pragma unroll 16
        for (int k = 0; k < H1; k++)
            s0 = fmaf(h1s[r * H1 + k], sW2[k * H2 + j], s0);
        h2s[r * H2 + j] = fmaxf(s0 + __ldg(&b2[j]), 0.0f);
    }
    __syncthreads();

    // GEMM3: 16 outputs (8 rows x 2 logits)
    if (tid < ROWS * OUTC) {
        const int r = tid >> 1;
        const int j = tid & 1;
        float s = __ldg(&b3[j]);
        #pragma unroll 8
        for (int cc = 0; cc < H2; cc++)
            s = fmaf(h2s[r * H2 + cc], __ldg(&W3[cc * OUTC + j]), s);
        out[(size_t)(r0 + r) * OUTC + j] = s;
    }
}

// ---------------------------------------------------------------------------
extern "C" void kernel_launch(void* const* d_in, const int* in_sizes, int n_in,
                              void* d_out, int out_size) {
    const float* hidden = (const float*)d_in[0];
    const void*  mask   = d_in[1];
    const float* W1 = (const float*)d_in[2];
    const float* b1 = (const float*)d_in[3];
    const float* W2 = (const float*)d_in[4];
    const float* b2 = (const float*)d_in[5];
    const float* W3 = (const float*)d_in[6];
    const float* b3 = (const float*)d_in[7];
    float* out = (float*)d_out;

    static int smem_set = 0;
    if (!smem_set) {
        cudaFuncSetAttribute(gemm1_kernel,
                             cudaFuncAttributeMaxDynamicSharedMemorySize,
                             G1_SMEM * sizeof(float));
        cudaFuncSetAttribute(gemm23_kernel,
                             cudaFuncAttributeMaxDynamicSharedMemorySize,
                             G2_SMEM * sizeof(float));
        smem_set = 1;
    }

    reduce_kernel<<<QTRS * BB, 192>>>(hidden, mask);
    gemm1_kernel<<<SLICES * (BB / ROWS), 512, G1_SMEM * sizeof(float)>>>(W1);
    gemm23_kernel<<<BB / ROWS, 512, G2_SMEM * sizeof(float)>>>(b1, W2, b2, W3, b3, out);
}

// round 13
// speedup vs baseline: 1.3399x; 1.3399x over previous
#include <cuda_runtime.h>
#include <cuda_bf16.h>

// Problem constants (SpectralClassifier: B=1024, S=128, D=768)
#define BB 1024
#define SS 128
#define DD 768
#define H1 256
#define H2 64
#define OUTC 2
#define ROWS 8
#define QTRS 4
#define DET_WORDS 256     // per-block detection sample (1KB, L2-broadcast)
#define KGRPS 8           // k-groups in MLP
#define KPER (DD / KGRPS) // 96 k per group
#define KCH 6             // k-steps per register chunk
#define NCH (KPER / KCH)  // 16 chunks

// Scratch (no cudaMalloc allowed).
__device__ float g_vp[QTRS * BB * DD];   // unscaled partial sums [quarter][b][d]

// packed dual-fp32 FMA (sm_100+)
#define FMA_F32X2(d, a, b, c) \
    asm("fma.rn.f32x2 %0, %1, %2, %3;" : "=l"(d) : "l"(a), "l"(b), "l"(c))

__device__ __forceinline__ void cpasync16(float* smem_dst, const float* gsrc) {
    unsigned saddr = (unsigned)__cvta_generic_to_shared(smem_dst);
    asm volatile("cp.async.cg.shared.global [%0], [%1], 16;" :: "r"(saddr), "l"(gsrc) : "memory");
}
#define CP_COMMIT()  asm volatile("cp.async.commit_group;" ::: "memory")
#define CP_WAIT(n)   asm volatile("cp.async.wait_group %0;" :: "n"(n) : "memory")

__device__ __forceinline__ bool mask_at(const void* mask, int idx, int mode) {
    if (mode == 0) return ((const int*)mask)[idx] != 0;
    if (mode == 1) return ((const float*)mask)[idx] != 0.0f;
    return ((const unsigned char*)mask)[idx] != 0;
}

// ---------------------------------------------------------------------------
// Kernel A: partial masked seq-sums with inline mask-dtype detection.
// 4096 blocks: blockIdx.x = b*4 + q. (At ~65% HBM — unchanged this round.)
// ---------------------------------------------------------------------------
__global__ void __launch_bounds__(192) reduce_kernel(
    const float* __restrict__ hidden, const void* __restrict__ mask)
{
    __shared__ int s_idx[32];
    __shared__ int s_cnt;
    __shared__ int s_mode;

    const int b   = blockIdx.x >> 2;
    const int q   = blockIdx.x & 3;
    const int lo  = (q == 0) ? 1 : (q * 32);
    const int nrows = (q == 0) ? 31 : 32;
    const int tid = threadIdx.x;

    {
        int bad_i = 0, bad_f = 0;
        const uint4* w4 = (const uint4*)mask;
        for (int i = tid; i < DET_WORDS / 4; i += 192) {
            uint4 v = __ldg(&w4[i]);
            unsigned arr[4] = {v.x, v.y, v.z, v.w};
            #pragma unroll
            for (int j = 0; j < 4; j++) {
                unsigned u = arr[j];
                if (u > 1u) bad_i = 1;
                float f = __uint_as_float(u);
                if (!(f == 0.0f || f == 1.0f)) bad_f = 1;
            }
        }
        bad_i = __any_sync(0xffffffffu, bad_i);
        bad_f = __any_sync(0xffffffffu, bad_f);
        if (tid == 0) s_mode = 0;
        __syncthreads();
        if ((tid & 31) == 0) {
            int mode = (!bad_i) ? 0 : ((!bad_f) ? 1 : 2);
            atomicMax(&s_mode, mode);
        }
        __syncthreads();
    }
    const int mode = s_mode;

    if (tid < 32) {
        bool m = (tid < nrows) && mask_at(mask, b * SS + lo + tid, mode);
        unsigned bal = __ballot_sync(0xffffffffu, m);
        if (m) s_idx[__popc(bal & ((1u << tid) - 1u))] = lo + tid;
        if (tid == 0) s_cnt = __popc(bal);
    }
    __syncthreads();

    const int cnt = s_cnt;
    const float4* hp = (const float4*)(hidden + (size_t)b * SS * DD);

    float4 a0 = make_float4(0.f, 0.f, 0.f, 0.f);
    float4 a1 = make_float4(0.f, 0.f, 0.f, 0.f);
    float4 a2 = make_float4(0.f, 0.f, 0.f, 0.f);
    float4 a3 = make_float4(0.f, 0.f, 0.f, 0.f);

    int i = 0;
    for (; i + 8 <= cnt; i += 8) {
        float4 x[8];
        #pragma unroll
        for (int u = 0; u < 8; u++)
            x[u] = __ldcs(&hp[s_idx[i + u] * (DD / 4) + tid]);
        a0.x += x[0].x; a0.y += x[0].y; a0.z += x[0].z; a0.w += x[0].w;
        a1.x += x[1].x; a1.y += x[1].y; a1.z += x[1].z; a1.w += x[1].w;
        a2.x += x[2].x; a2.y += x[2].y; a2.z += x[2].z; a2.w += x[2].w;
        a3.x += x[3].x; a3.y += x[3].y; a3.z += x[3].z; a3.w += x[3].w;
        a0.x += x[4].x; a0.y += x[4].y; a0.z += x[4].z; a0.w += x[4].w;
        a1.x += x[5].x; a1.y += x[5].y; a1.z += x[5].z; a1.w += x[5].w;
        a2.x += x[6].x; a2.y += x[6].y; a2.z += x[6].z; a2.w += x[6].w;
        a3.x += x[7].x; a3.y += x[7].y; a3.z += x[7].z; a3.w += x[7].w;
    }
    for (; i < cnt; i++) {
        float4 x0 = __ldcs(&hp[s_idx[i] * (DD / 4) + tid]);
        a0.x += x0.x; a0.y += x0.y; a0.z += x0.z; a0.w += x0.w;
    }

    float4 r;
    r.x = (a0.x + a1.x) + (a2.x + a3.x);
    r.y = (a0.y + a1.y) + (a2.y + a3.y);
    r.z = (a0.z + a1.z) + (a2.z + a3.z);
    r.w = (a0.w + a1.w) + (a2.w + a3.w);
    ((float4*)(g_vp + (size_t)(q * BB + b) * DD))[tid] = r;
}

// ---------------------------------------------------------------------------
// Kernel B: full MLP per 8-row tile. 128 blocks x 1024 threads (32 warps/SM).
// W1 streamed LDG.64 -> registers (no smem echo), KCH=6 ping-pong, zero
// barriers in the mainloop. Thread: 2 cols x 8 rows x 96 k;
// kg = tid>>7 (8 kgroups), c = tid&127 (col pair 2c, 2c+1).
// Dynamic smem (floats):
//   vs[DD*ROWS]        : 0     .. 6144
//   h1p[KGRPS][2048]   : 6144  .. 22528
//   h1s[ROWS*H1]       : 22528 .. 24576
//   sW2[H1*H2]         : 24576 .. 40960
//   h2s[ROWS*H2]       : 40960 .. 41472
// ---------------------------------------------------------------------------
#define SMEM_FLOATS 41472
#define OFF_VS   0
#define OFF_H1P  6144
#define OFF_H1S  22528
#define OFF_W2   24576
#define OFF_H2S  40960

// one k-step: w2v = float2 weights for 2 cols; vkp -> vs[k][0]
#define KSTEP2(w2v, vkp) do {                                             \
    unsigned long long w0, w1;                                            \
    asm("mov.b64 %0, {%1, %1};" : "=l"(w0) : "f"((w2v).x));               \
    asm("mov.b64 %0, {%1, %1};" : "=l"(w1) : "f"((w2v).y));               \
    const ulonglong2 va = *(const ulonglong2*)(vkp);                      \
    const ulonglong2 vb = *(const ulonglong2*)((vkp) + 4);                \
    FMA_F32X2(accp[0], va.x, w0, accp[0]);                                \
    FMA_F32X2(accp[1], va.y, w0, accp[1]);                                \
    FMA_F32X2(accp[2], vb.x, w0, accp[2]);                                \
    FMA_F32X2(accp[3], vb.y, w0, accp[3]);                                \
    FMA_F32X2(accp[4], va.x, w1, accp[4]);                                \
    FMA_F32X2(accp[5], va.y, w1, accp[5]);                                \
    FMA_F32X2(accp[6], vb.x, w1, accp[6]);                                \
    FMA_F32X2(accp[7], vb.y, w1, accp[7]);                                \
} while (0)

__global__ void __launch_bounds__(1024, 1) mlp_kernel(
    const float* __restrict__ W1, const float* __restrict__ b1,
    const float* __restrict__ W2, const float* __restrict__ b2,
    const float* __restrict__ W3, const float* __restrict__ b3,
    float* __restrict__ out)
{
    extern __shared__ float smf[];
    float* vs  = smf + OFF_VS;
    float* h1p = smf + OFF_H1P;
    float* h1s = smf + OFF_H1S;
    float* sW2 = smf + OFF_W2;
    float* h2s = smf + OFF_H2S;

    const int tid = threadIdx.x;
    const int c   = tid & 127;            // col pair: cols 2c, 2c+1
    const int kg  = tid >> 7;             // 0..7
    const int r0  = blockIdx.x * ROWS;
    const float inv127 = 1.0f / 127.0f;

    // --- Prologue: stage W2 via cp.async ---
    #pragma unroll
    for (int i = 0; i < H1 * H2 / 4; i += 1024)
        cpasync16(&sW2[(i + tid) * 4], &W2[(i + tid) * 4]);
    CP_COMMIT();

    // --- Stage v rows: v = (sum of 4 quarter partials)/127, layout [k][r] ---
    #pragma unroll
    for (int ii = 0; ii < 2; ii++) {
        int idx = ii * 1024 + tid;         // 0..2047, need < 1536
        if (idx < ROWS * (DD / 4)) {
            int r  = idx / (DD / 4);
            int c4 = idx % (DD / 4);
            const float4* p0 = (const float4*)(g_vp + (size_t)(0 * BB + r0 + r) * DD);
            const float4* p1 = (const float4*)(g_vp + (size_t)(1 * BB + r0 + r) * DD);
            const float4* p2 = (const float4*)(g_vp + (size_t)(2 * BB + r0 + r) * DD);
            const float4* p3 = (const float4*)(g_vp + (size_t)(3 * BB + r0 + r) * DD);
            float4 u0 = __ldg(&p0[c4]);
            float4 u1 = __ldg(&p1[c4]);
            float4 u2 = __ldg(&p2[c4]);
            float4 u3 = __ldg(&p3[c4]);
            float* dst = &vs[(c4 * 4) * ROWS + r];
            dst[0 * ROWS] = ((u0.x + u1.x) + (u2.x + u3.x)) * inv127;
            dst[1 * ROWS] = ((u0.y + u1.y) + (u2.y + u3.y)) * inv127;
            dst[2 * ROWS] = ((u0.z + u1.z) + (u2.z + u3.z)) * inv127;
            dst[3 * ROWS] = ((u0.w + u1.w) + (u2.w + u3.w)) * inv127;
        }
    }
    __syncthreads();

    // --- GEMM1 mainloop: 96 k = 16 chunks of 6, ping-pong, zero barriers ---
    unsigned long long accp[8];
    #pragma unroll
    for (int j = 0; j < 8; j++) accp[j] = 0ull;

    const float2* wp = (const float2*)W1 + (size_t)(kg * KPER) * (H1 / 2) + c;
    const float*  vg = &vs[(kg * KPER) * ROWS];

    float2 wA[KCH], wB[KCH];
    #pragma unroll
    for (int u = 0; u < KCH; u++)
        wA[u] = __ldg(wp + u * (H1 / 2));
    wp += KCH * (H1 / 2);

    #pragma unroll 1
    for (int it = 0; it < NCH / 2; it++) {
        #pragma unroll
        for (int u = 0; u < KCH; u++)
            wB[u] = __ldg(wp + u * (H1 / 2));
        wp += KCH * (H1 / 2);
        {
            const float* vk = vg + (it * 2 * KCH) * ROWS;
            #pragma unroll
            for (int u = 0; u < KCH; u++)
                KSTEP2(wA[u], vk + u * ROWS);
        }
        if (it < NCH / 2 - 1) {
            #pragma unroll
            for (int u = 0; u < KCH; u++)
                wA[u] = __ldg(wp + u * (H1 / 2));
            wp += KCH * (H1 / 2);
        }
        {
            const float* vk = vg + (it * 2 * KCH + KCH) * ROWS;
            #pragma unroll
            for (int u = 0; u < KCH; u++)
                KSTEP2(wB[u], vk + u * ROWS);
        }
    }

    // --- Write 8 kgroup partials: h1p[kg][row*256 + 2c + {0,1}] ---
    __syncthreads();
    {
        float* hp = h1p + kg * (ROWS * H1);
        #pragma unroll
        for (int j = 0; j < 4; j++) {
            float lo0, hi0, lo1, hi1;
            asm("mov.b64 {%0, %1}, %2;" : "=f"(lo0), "=f"(hi0) : "l"(accp[j]));
            asm("mov.b64 {%0, %1}, %2;" : "=f"(lo1), "=f"(hi1) : "l"(accp[4 + j]));
            *(float2*)&hp[(2 * j) * H1 + 2 * c]     = make_float2(lo0, lo1);
            *(float2*)&hp[(2 * j + 1) * H1 + 2 * c] = make_float2(hi0, hi1);
        }
    }
    __syncthreads();

    // --- Reduce 8 partials -> h1s (bias + relu). 1024 threads x 2 floats ---
    {
        const int idx = tid * 2;           // 0..2046
        const int col = idx & (H1 - 1);
        float2 s = *(const float2*)&h1p[idx];
        #pragma unroll
        for (int g = 1; g < KGRPS; g++) {
            float2 p = *(const float2*)&h1p[g * (ROWS * H1) + idx];
            s.x += p.x; s.y += p.y;
        }
        float2 bb = *(const float2*)&b1[col];
        s.x = fmaxf(s.x + bb.x, 0.0f);
        s.y = fmaxf(s.y + bb.y, 0.0f);
        *(float2*)&h1s[idx] = s;
    }
    CP_WAIT(0);
    __syncthreads();

    // --- GEMM2 (smem): threads 0..511 -> (r = t>>6, j = t&63) ---
    if (tid < 512) {
        const int j = tid & (H2 - 1);
        const int r = tid >> 6;            // 0..7
        float s0 = 0.0f;
        #pragma unroll 16
        for (int k = 0; k < H1; k++)
            s0 = fmaf(h1s[r * H1 + k], sW2[k * H2 + j], s0);
        h2s[r * H2 + j] = fmaxf(s0 + __ldg(&b2[j]), 0.0f);
    }
    __syncthreads();

    // --- GEMM3: 16 outputs (8 rows x 2 logits) ---
    if (tid < ROWS * OUTC) {
        const int r = tid >> 1;
        const int j = tid & 1;
        float s = __ldg(&b3[j]);
        #pragma unroll 8
        for (int cc = 0; cc < H2; cc++)
            s = fmaf(h2s[r * H2 + cc], __ldg(&W3[cc * OUTC + j]), s);
        out[(size_t)(r0 + r) * OUTC + j] = s;
    }
}

// ---------------------------------------------------------------------------
extern "C" void kernel_launch(void* const* d_in, const int* in_sizes, int n_in,
                              void* d_out, int out_size) {
    const float* hidden = (const float*)d_in[0];
    const void*  mask   = d_in[1];
    const float* W1 = (const float*)d_in[2];
    const float* b1 = (const float*)d_in[3];
    const float* W2 = (const float*)d_in[4];
    const float* b2 = (const float*)d_in[5];
    const float* W3 = (const float*)d_in[6];
    const float* b3 = (const float*)d_in[7];
    float* out = (float*)d_out;

    static int smem_set = 0;
    if (!smem_set) {
        cudaFuncSetAttribute(mlp_kernel,
                             cudaFuncAttributeMaxDynamicSharedMemorySize,
                             SMEM_FLOATS * sizeof(float));
        smem_set = 1;
    }

    reduce_kernel<<<QTRS * BB, 192>>>(hidden, mask);
    mlp_kernel<<<BB / ROWS, 1024, SMEM_FLOATS * sizeof(float)>>>(
        W1, b1, W2, b2, W3, b3, out);
}

// round 14
// speedup vs baseline: 1.3406x; 1.0005x over previous
#include <cuda_runtime.h>
#include <cuda_bf16.h>

// Problem constants (SpectralClassifier: B=1024, S=128, D=768)
#define BB 1024
#define SS 128
#define DD 768
#define H1 256
#define H2 64
#define OUTC 2
#define ROWS 8
#define QTRS 4
#define DET_WORDS 256     // per-block detection sample (1KB, L2-broadcast)
#define KGRPS 8           // k-groups in MLP
#define KPER (DD / KGRPS) // 96 k per group
#define KCH 6             // k-steps per register chunk
#define NCH (KPER / KCH)  // 16 chunks

// Scratch (no cudaMalloc allowed).
__device__ float g_vp[QTRS * BB * DD];   // unscaled partial sums [quarter][b][d]

// packed dual-fp32 FMA (sm_100+)
#define FMA_F32X2(d, a, b, c) \
    asm("fma.rn.f32x2 %0, %1, %2, %3;" : "=l"(d) : "l"(a), "l"(b), "l"(c))

__device__ __forceinline__ void cpasync16(float* smem_dst, const float* gsrc) {
    unsigned saddr = (unsigned)__cvta_generic_to_shared(smem_dst);
    asm volatile("cp.async.cg.shared.global [%0], [%1], 16;" :: "r"(saddr), "l"(gsrc) : "memory");
}
#define CP_COMMIT()  asm volatile("cp.async.commit_group;" ::: "memory")
#define CP_WAIT(n)   asm volatile("cp.async.wait_group %0;" :: "n"(n) : "memory")

__device__ __forceinline__ bool mask_at(const void* mask, int idx, int mode) {
    if (mode == 0) return ((const int*)mask)[idx] != 0;
    if (mode == 1) return ((const float*)mask)[idx] != 0.0f;
    return ((const unsigned char*)mask)[idx] != 0;
}

// ---------------------------------------------------------------------------
// Kernel A: partial masked seq-sums with inline mask-dtype detection.
// 4096 blocks: blockIdx.x = b*4 + q. (At ~65% HBM — unchanged this round.)
// ---------------------------------------------------------------------------
__global__ void __launch_bounds__(192) reduce_kernel(
    const float* __restrict__ hidden, const void* __restrict__ mask)
{
    __shared__ int s_idx[32];
    __shared__ int s_cnt;
    __shared__ int s_mode;

    const int b   = blockIdx.x >> 2;
    const int q   = blockIdx.x & 3;
    const int lo  = (q == 0) ? 1 : (q * 32);
    const int nrows = (q == 0) ? 31 : 32;
    const int tid = threadIdx.x;

    {
        int bad_i = 0, bad_f = 0;
        const uint4* w4 = (const uint4*)mask;
        for (int i = tid; i < DET_WORDS / 4; i += 192) {
            uint4 v = __ldg(&w4[i]);
            unsigned arr[4] = {v.x, v.y, v.z, v.w};
            #pragma unroll
            for (int j = 0; j < 4; j++) {
                unsigned u = arr[j];
                if (u > 1u) bad_i = 1;
                float f = __uint_as_float(u);
                if (!(f == 0.0f || f == 1.0f)) bad_f = 1;
            }
        }
        bad_i = __any_sync(0xffffffffu, bad_i);
        bad_f = __any_sync(0xffffffffu, bad_f);
        if (tid == 0) s_mode = 0;
        __syncthreads();
        if ((tid & 31) == 0) {
            int mode = (!bad_i) ? 0 : ((!bad_f) ? 1 : 2);
            atomicMax(&s_mode, mode);
        }
        __syncthreads();
    }
    const int mode = s_mode;

    if (tid < 32) {
        bool m = (tid < nrows) && mask_at(mask, b * SS + lo + tid, mode);
        unsigned bal = __ballot_sync(0xffffffffu, m);
        if (m) s_idx[__popc(bal & ((1u << tid) - 1u))] = lo + tid;
        if (tid == 0) s_cnt = __popc(bal);
    }
    __syncthreads();

    const int cnt = s_cnt;
    const float4* hp = (const float4*)(hidden + (size_t)b * SS * DD);

    float4 a0 = make_float4(0.f, 0.f, 0.f, 0.f);
    float4 a1 = make_float4(0.f, 0.f, 0.f, 0.f);
    float4 a2 = make_float4(0.f, 0.f, 0.f, 0.f);
    float4 a3 = make_float4(0.f, 0.f, 0.f, 0.f);

    int i = 0;
    for (; i + 8 <= cnt; i += 8) {
        float4 x[8];
        #pragma unroll
        for (int u = 0; u < 8; u++)
            x[u] = __ldcs(&hp[s_idx[i + u] * (DD / 4) + tid]);
        a0.x += x[0].x; a0.y += x[0].y; a0.z += x[0].z; a0.w += x[0].w;
        a1.x += x[1].x; a1.y += x[1].y; a1.z += x[1].z; a1.w += x[1].w;
        a2.x += x[2].x; a2.y += x[2].y; a2.z += x[2].z; a2.w += x[2].w;
        a3.x += x[3].x; a3.y += x[3].y; a3.z += x[3].z; a3.w += x[3].w;
        a0.x += x[4].x; a0.y += x[4].y; a0.z += x[4].z; a0.w += x[4].w;
        a1.x += x[5].x; a1.y += x[5].y; a1.z += x[5].z; a1.w += x[5].w;
        a2.x += x[6].x; a2.y += x[6].y; a2.z += x[6].z; a2.w += x[6].w;
        a3.x += x[7].x; a3.y += x[7].y; a3.z += x[7].z; a3.w += x[7].w;
    }
    for (; i < cnt; i++) {
        float4 x0 = __ldcs(&hp[s_idx[i] * (DD / 4) + tid]);
        a0.x += x0.x; a0.y += x0.y; a0.z += x0.z; a0.w += x0.w;
    }

    float4 r;
    r.x = (a0.x + a1.x) + (a2.x + a3.x);
    r.y = (a0.y + a1.y) + (a2.y + a3.y);
    r.z = (a0.z + a1.z) + (a2.z + a3.z);
    r.w = (a0.w + a1.w) + (a2.w + a3.w);
    ((float4*)(g_vp + (size_t)(q * BB + b) * DD))[tid] = r;
}

// ---------------------------------------------------------------------------
// Kernel B: full MLP per 8-row tile. 128 blocks x 1024 threads (32 warps/SM).
// W1 streamed LDG.64 -> registers (no smem echo), KCH=6 ping-pong, zero
// barriers in the mainloop. Thread: 2 cols x 8 rows x 96 k;
// kg = tid>>7 (8 kgroups), c = tid&127 (col pair 2c, 2c+1).
// Dynamic smem (floats):
//   vs[DD*ROWS]        : 0     .. 6144
//   h1p[KGRPS][2048]   : 6144  .. 22528
//   h1s[ROWS*H1]       : 22528 .. 24576
//   sW2[H1*H2]         : 24576 .. 40960
//   h2s[ROWS*H2]       : 40960 .. 41472
// ---------------------------------------------------------------------------
#define SMEM_FLOATS 41472
#define OFF_VS   0
#define OFF_H1P  6144
#define OFF_H1S  22528
#define OFF_W2   24576
#define OFF_H2S  40960

// one k-step: w2v = float2 weights for 2 cols; vkp -> vs[k][0]
#define KSTEP2(w2v, vkp) do {                                             \
    unsigned long long w0, w1;                                            \
    asm("mov.b64 %0, {%1, %1};" : "=l"(w0) : "f"((w2v).x));               \
    asm("mov.b64 %0, {%1, %1};" : "=l"(w1) : "f"((w2v).y));               \
    const ulonglong2 va = *(const ulonglong2*)(vkp);                      \
    const ulonglong2 vb = *(const ulonglong2*)((vkp) + 4);                \
    FMA_F32X2(accp[0], va.x, w0, accp[0]);                                \
    FMA_F32X2(accp[1], va.y, w0, accp[1]);                                \
    FMA_F32X2(accp[2], vb.x, w0, accp[2]);                                \
    FMA_F32X2(accp[3], vb.y, w0, accp[3]);                                \
    FMA_F32X2(accp[4], va.x, w1, accp[4]);                                \
    FMA_F32X2(accp[5], va.y, w1, accp[5]);                                \
    FMA_F32X2(accp[6], vb.x, w1, accp[6]);                                \
    FMA_F32X2(accp[7], vb.y, w1, accp[7]);                                \
} while (0)

__global__ void __launch_bounds__(1024, 1) mlp_kernel(
    const float* __restrict__ W1, const float* __restrict__ b1,
    const float* __restrict__ W2, const float* __restrict__ b2,
    const float* __restrict__ W3, const float* __restrict__ b3,
    float* __restrict__ out)
{
    extern __shared__ float smf[];
    float* vs  = smf + OFF_VS;
    float* h1p = smf + OFF_H1P;
    float* h1s = smf + OFF_H1S;
    float* sW2 = smf + OFF_W2;
    float* h2s = smf + OFF_H2S;

    const int tid = threadIdx.x;
    const int c   = tid & 127;            // col pair: cols 2c, 2c+1
    const int kg  = tid >> 7;             // 0..7
    const int r0  = blockIdx.x * ROWS;
    const float inv127 = 1.0f / 127.0f;

    // --- Prologue: stage W2 via cp.async ---
    #pragma unroll
    for (int i = 0; i < H1 * H2 / 4; i += 1024)
        cpasync16(&sW2[(i + tid) * 4], &W2[(i + tid) * 4]);
    CP_COMMIT();

    // --- Stage v rows: v = (sum of 4 quarter partials)/127, layout [k][r] ---
    #pragma unroll
    for (int ii = 0; ii < 2; ii++) {
        int idx = ii * 1024 + tid;         // 0..2047, need < 1536
        if (idx < ROWS * (DD / 4)) {
            int r  = idx / (DD / 4);
            int c4 = idx % (DD / 4);
            const float4* p0 = (const float4*)(g_vp + (size_t)(0 * BB + r0 + r) * DD);
            const float4* p1 = (const float4*)(g_vp + (size_t)(1 * BB + r0 + r) * DD);
            const float4* p2 = (const float4*)(g_vp + (size_t)(2 * BB + r0 + r) * DD);
            const float4* p3 = (const float4*)(g_vp + (size_t)(3 * BB + r0 + r) * DD);
            float4 u0 = __ldg(&p0[c4]);
            float4 u1 = __ldg(&p1[c4]);
            float4 u2 = __ldg(&p2[c4]);
            float4 u3 = __ldg(&p3[c4]);
            float* dst = &vs[(c4 * 4) * ROWS + r];
            dst[0 * ROWS] = ((u0.x + u1.x) + (u2.x + u3.x)) * inv127;
            dst[1 * ROWS] = ((u0.y + u1.y) + (u2.y + u3.y)) * inv127;
            dst[2 * ROWS] = ((u0.z + u1.z) + (u2.z + u3.z)) * inv127;
            dst[3 * ROWS] = ((u0.w + u1.w) + (u2.w + u3.w)) * inv127;
        }
    }
    __syncthreads();

    // --- GEMM1 mainloop: 96 k = 16 chunks of 6, ping-pong, zero barriers ---
    unsigned long long accp[8];
    #pragma unroll
    for (int j = 0; j < 8; j++) accp[j] = 0ull;

    const float2* wp = (const float2*)W1 + (size_t)(kg * KPER) * (H1 / 2) + c;
    const float*  vg = &vs[(kg * KPER) * ROWS];

    float2 wA[KCH], wB[KCH];
    #pragma unroll
    for (int u = 0; u < KCH; u++)
        wA[u] = __ldg(wp + u * (H1 / 2));
    wp += KCH * (H1 / 2);

    #pragma unroll 1
    for (int it = 0; it < NCH / 2; it++) {
        #pragma unroll
        for (int u = 0; u < KCH; u++)
            wB[u] = __ldg(wp + u * (H1 / 2));
        wp += KCH * (H1 / 2);
        {
            const float* vk = vg + (it * 2 * KCH) * ROWS;
            #pragma unroll
            for (int u = 0; u < KCH; u++)
                KSTEP2(wA[u], vk + u * ROWS);
        }
        if (it < NCH / 2 - 1) {
            #pragma unroll
            for (int u = 0; u < KCH; u++)
                wA[u] = __ldg(wp + u * (H1 / 2));
            wp += KCH * (H1 / 2);
        }
        {
            const float* vk = vg + (it * 2 * KCH + KCH) * ROWS;
            #pragma unroll
            for (int u = 0; u < KCH; u++)
                KSTEP2(wB[u], vk + u * ROWS);
        }
    }

    // --- Write 8 kgroup partials: h1p[kg][row*256 + 2c + {0,1}] ---
    __syncthreads();
    {
        float* hp = h1p + kg * (ROWS * H1);
        #pragma unroll
        for (int j = 0; j < 4; j++) {
            float lo0, hi0, lo1, hi1;
            asm("mov.b64 {%0, %1}, %2;" : "=f"(lo0), "=f"(hi0) : "l"(accp[j]));
            asm("mov.b64 {%0, %1}, %2;" : "=f"(lo1), "=f"(hi1) : "l"(accp[4 + j]));
            *(float2*)&hp[(2 * j) * H1 + 2 * c]     = make_float2(lo0, lo1);
            *(float2*)&hp[(2 * j + 1) * H1 + 2 * c] = make_float2(hi0, hi1);
        }
    }
    __syncthreads();

    // --- Reduce 8 partials -> h1s (bias + relu). 1024 threads x 2 floats ---
    {
        const int idx = tid * 2;           // 0..2046
        const int col = idx & (H1 - 1);
        float2 s = *(const float2*)&h1p[idx];
        #pragma unroll
        for (int g = 1; g < KGRPS; g++) {
            float2 p = *(const float2*)&h1p[g * (ROWS * H1) + idx];
            s.x += p.x; s.y += p.y;
        }
        float2 bb = *(const float2*)&b1[col];
        s.x = fmaxf(s.x + bb.x, 0.0f);
        s.y = fmaxf(s.y + bb.y, 0.0f);
        *(float2*)&h1s[idx] = s;
    }
    CP_WAIT(0);
    __syncthreads();

    // --- GEMM2 (smem): threads 0..511 -> (r = t>>6, j = t&63) ---
    if (tid < 512) {
        const int j = tid & (H2 - 1);
        const int r = tid >> 6;            // 0..7
        float s0 = 0.0f;
        #pragma unroll 16
        for (int k = 0; k < H1; k++)
            s0 = fmaf(h1s[r * H1 + k], sW2[k * H2 + j], s0);
        h2s[r * H2 + j] = fmaxf(s0 + __ldg(&b2[j]), 0.0f);
    }
    __syncthreads();

    // --- GEMM3: 16 outputs (8 rows x 2 logits) ---
    if (tid < ROWS * OUTC) {
        const int r = tid >> 1;
        const int j = tid & 1;
        float s = __ldg(&b3[j]);
        #pragma unroll 8
        for (int cc = 0; cc < H2; cc++)
            s = fmaf(h2s[r * H2 + cc], __ldg(&W3[cc * OUTC + j]), s);
        out[(size_t)(r0 + r) * OUTC + j] = s;
    }
}

// ---------------------------------------------------------------------------
extern "C" void kernel_launch(void* const* d_in, const int* in_sizes, int n_in,
                              void* d_out, int out_size) {
    const float* hidden = (const float*)d_in[0];
    const void*  mask   = d_in[1];
    const float* W1 = (const float*)d_in[2];
    const float* b1 = (const float*)d_in[3];
    const float* W2 = (const float*)d_in[4];
    const float* b2 = (const float*)d_in[5];
    const float* W3 = (const float*)d_in[6];
    const float* b3 = (const float*)d_in[7];
    float* out = (float*)d_out;

    static int smem_set = 0;
    if (!smem_set) {
        cudaFuncSetAttribute(mlp_kernel,
                             cudaFuncAttributeMaxDynamicSharedMemorySize,
                             SMEM_FLOATS * sizeof(float));
        smem_set = 1;
    }

    reduce_kernel<<<QTRS * BB, 192>>>(hidden, mask);
    mlp_kernel<<<BB / ROWS, 1024, SMEM_FLOATS * sizeof(float)>>>(
        W1, b1, W2, b2, W3, b3, out);
}

// round 15
// speedup vs baseline: 1.3788x; 1.0285x over previous
#include <cuda_runtime.h>
#include <cuda_bf16.h>

// Problem constants (SpectralClassifier: B=1024, S=128, D=768)
#define BB 1024
#define SS 128
#define DD 768
#define H1 256
#define H2 64
#define OUTC 2
#define ROWS 8
#define QTRS 4
#define DET_WORDS 256     // per-block detection sample (1KB, L2-broadcast)
#define KGRPS 8           // k-groups in MLP
#define KPER (DD / KGRPS) // 96 k per group
#define KCH 6             // k-steps per register chunk
#define NCH (KPER / KCH)  // 16 chunks

// Scratch (no cudaMalloc allowed).
__device__ float g_vp[QTRS * BB * DD];   // unscaled partial sums [quarter][b][d]

// packed dual-fp32 FMA (sm_100+)
#define FMA_F32X2(d, a, b, c) \
    asm("fma.rn.f32x2 %0, %1, %2, %3;" : "=l"(d) : "l"(a), "l"(b), "l"(c))

__device__ __forceinline__ void cpasync16(float* smem_dst, const float* gsrc) {
    unsigned saddr = (unsigned)__cvta_generic_to_shared(smem_dst);
    asm volatile("cp.async.cg.shared.global [%0], [%1], 16;" :: "r"(saddr), "l"(gsrc) : "memory");
}
#define CP_COMMIT()  asm volatile("cp.async.commit_group;" ::: "memory")
#define CP_WAIT(n)   asm volatile("cp.async.wait_group %0;" :: "n"(n) : "memory")

__device__ __forceinline__ bool mask_at(const void* mask, int idx, int mode) {
    if (mode == 0) return ((const int*)mask)[idx] != 0;
    if (mode == 1) return ((const float*)mask)[idx] != 0.0f;
    return ((const unsigned char*)mask)[idx] != 0;
}

// ---------------------------------------------------------------------------
// Kernel A: partial masked seq-sums with inline mask-dtype detection.
// 4096 blocks: blockIdx.x = b*4 + q. Register-capped (192,8) for 8 blocks/SM:
// higher occupancy -> more independent gather streams -> higher HBM%.
// ---------------------------------------------------------------------------
__global__ void __launch_bounds__(192, 8) reduce_kernel(
    const float* __restrict__ hidden, const void* __restrict__ mask)
{
    __shared__ int s_idx[32];
    __shared__ int s_cnt;
    __shared__ int s_mode;

    const int b   = blockIdx.x >> 2;
    const int q   = blockIdx.x & 3;
    const int lo  = (q == 0) ? 1 : (q * 32);
    const int nrows = (q == 0) ? 31 : 32;
    const int tid = threadIdx.x;

    {
        int bad_i = 0, bad_f = 0;
        const uint4* w4 = (const uint4*)mask;
        for (int i = tid; i < DET_WORDS / 4; i += 192) {
            uint4 v = __ldg(&w4[i]);
            unsigned arr[4] = {v.x, v.y, v.z, v.w};
            #pragma unroll
            for (int j = 0; j < 4; j++) {
                unsigned u = arr[j];
                if (u > 1u) bad_i = 1;
                float f = __uint_as_float(u);
                if (!(f == 0.0f || f == 1.0f)) bad_f = 1;
            }
        }
        bad_i = __any_sync(0xffffffffu, bad_i);
        bad_f = __any_sync(0xffffffffu, bad_f);
        if (tid == 0) s_mode = 0;
        __syncthreads();
        if ((tid & 31) == 0) {
            int mode = (!bad_i) ? 0 : ((!bad_f) ? 1 : 2);
            atomicMax(&s_mode, mode);
        }
        __syncthreads();
    }
    const int mode = s_mode;

    if (tid < 32) {
        bool m = (tid < nrows) && mask_at(mask, b * SS + lo + tid, mode);
        unsigned bal = __ballot_sync(0xffffffffu, m);
        if (m) s_idx[__popc(bal & ((1u << tid) - 1u))] = lo + tid;
        if (tid == 0) s_cnt = __popc(bal);
    }
    __syncthreads();

    const int cnt = s_cnt;
    const float4* hp = (const float4*)(hidden + (size_t)b * SS * DD);

    float4 a0 = make_float4(0.f, 0.f, 0.f, 0.f);
    float4 a1 = make_float4(0.f, 0.f, 0.f, 0.f);
    float4 a2 = make_float4(0.f, 0.f, 0.f, 0.f);
    float4 a3 = make_float4(0.f, 0.f, 0.f, 0.f);

    int i = 0;
    for (; i + 4 <= cnt; i += 4) {
        float4 x0 = __ldcs(&hp[s_idx[i]     * (DD / 4) + tid]);
        float4 x1 = __ldcs(&hp[s_idx[i + 1] * (DD / 4) + tid]);
        float4 x2 = __ldcs(&hp[s_idx[i + 2] * (DD / 4) + tid]);
        float4 x3 = __ldcs(&hp[s_idx[i + 3] * (DD / 4) + tid]);
        a0.x += x0.x; a0.y += x0.y; a0.z += x0.z; a0.w += x0.w;
        a1.x += x1.x; a1.y += x1.y; a1.z += x1.z; a1.w += x1.w;
        a2.x += x2.x; a2.y += x2.y; a2.z += x2.z; a2.w += x2.w;
        a3.x += x3.x; a3.y += x3.y; a3.z += x3.z; a3.w += x3.w;
    }
    for (; i < cnt; i++) {
        float4 x0 = __ldcs(&hp[s_idx[i] * (DD / 4) + tid]);
        a0.x += x0.x; a0.y += x0.y; a0.z += x0.z; a0.w += x0.w;
    }

    float4 r;
    r.x = (a0.x + a1.x) + (a2.x + a3.x);
    r.y = (a0.y + a1.y) + (a2.y + a3.y);
    r.z = (a0.z + a1.z) + (a2.z + a3.z);
    r.w = (a0.w + a1.w) + (a2.w + a3.w);
    ((float4*)(g_vp + (size_t)(q * BB + b) * DD))[tid] = r;
}

// ---------------------------------------------------------------------------
// Kernel B: full MLP per 8-row tile. 128 blocks x 1024 threads (32 warps/SM).
// W1 streamed LDG.64 -> registers (no smem echo), KCH=6 ping-pong, zero
// barriers in the mainloop. Thread: 2 cols x 8 rows x 96 k;
// kg = tid>>7 (8 kgroups), c = tid&127 (col pair 2c, 2c+1).  (R14 winner.)
// Dynamic smem (floats):
//   vs[DD*ROWS]        : 0     .. 6144
//   h1p[KGRPS][2048]   : 6144  .. 22528
//   h1s[ROWS*H1]       : 22528 .. 24576
//   sW2[H1*H2]         : 24576 .. 40960
//   h2s[ROWS*H2]       : 40960 .. 41472
// ---------------------------------------------------------------------------
#define SMEM_FLOATS 41472
#define OFF_VS   0
#define OFF_H1P  6144
#define OFF_H1S  22528
#define OFF_W2   24576
#define OFF_H2S  40960

// one k-step: w2v = float2 weights for 2 cols; vkp -> vs[k][0]
#define KSTEP2(w2v, vkp) do {                                             \
    unsigned long long w0, w1;                                            \
    asm("mov.b64 %0, {%1, %1};" : "=l"(w0) : "f"((w2v).x));               \
    asm("mov.b64 %0, {%1, %1};" : "=l"(w1) : "f"((w2v).y));               \
    const ulonglong2 va = *(const ulonglong2*)(vkp);                      \
    const ulonglong2 vb = *(const ulonglong2*)((vkp) + 4);                \
    FMA_F32X2(accp[0], va.x, w0, accp[0]);                                \
    FMA_F32X2(accp[1], va.y, w0, accp[1]);                                \
    FMA_F32X2(accp[2], vb.x, w0, accp[2]);                                \
    FMA_F32X2(accp[3], vb.y, w0, accp[3]);                                \
    FMA_F32X2(accp[4], va.x, w1, accp[4]);                                \
    FMA_F32X2(accp[5], va.y, w1, accp[5]);                                \
    FMA_F32X2(accp[6], vb.x, w1, accp[6]);                                \
    FMA_F32X2(accp[7], vb.y, w1, accp[7]);                                \
} while (0)

__global__ void __launch_bounds__(1024, 1) mlp_kernel(
    const float* __restrict__ W1, const float* __restrict__ b1,
    const float* __restrict__ W2, const float* __restrict__ b2,
    const float* __restrict__ W3, const float* __restrict__ b3,
    float* __restrict__ out)
{
    extern __shared__ float smf[];
    float* vs  = smf + OFF_VS;
    float* h1p = smf + OFF_H1P;
    float* h1s = smf + OFF_H1S;
    float* sW2 = smf + OFF_W2;
    float* h2s = smf + OFF_H2S;

    const int tid = threadIdx.x;
    const int c   = tid & 127;            // col pair: cols 2c, 2c+1
    const int kg  = tid >> 7;             // 0..7
    const int r0  = blockIdx.x * ROWS;
    const float inv127 = 1.0f / 127.0f;

    // --- Prologue: stage W2 via cp.async ---
    #pragma unroll
    for (int i = 0; i < H1 * H2 / 4; i += 1024)
        cpasync16(&sW2[(i + tid) * 4], &W2[(i + tid) * 4]);
    CP_COMMIT();

    // --- Stage v rows: v = (sum of 4 quarter partials)/127, layout [k][r] ---
    #pragma unroll
    for (int ii = 0; ii < 2; ii++) {
        int idx = ii * 1024 + tid;         // 0..2047, need < 1536
        if (idx < ROWS * (DD / 4)) {
            int r  = idx / (DD / 4);
            int c4 = idx % (DD / 4);
            const float4* p0 = (const float4*)(g_vp + (size_t)(0 * BB + r0 + r) * DD);
            const float4* p1 = (const float4*)(g_vp + (size_t)(1 * BB + r0 + r) * DD);
            const float4* p2 = (const float4*)(g_vp + (size_t)(2 * BB + r0 + r) * DD);
            const float4* p3 = (const float4*)(g_vp + (size_t)(3 * BB + r0 + r) * DD);
            float4 u0 = __ldg(&p0[c4]);
            float4 u1 = __ldg(&p1[c4]);
            float4 u2 = __ldg(&p2[c4]);
            float4 u3 = __ldg(&p3[c4]);
            float* dst = &vs[(c4 * 4) * ROWS + r];
            dst[0 * ROWS] = ((u0.x + u1.x) + (u2.x + u3.x)) * inv127;
            dst[1 * ROWS] = ((u0.y + u1.y) + (u2.y + u3.y)) * inv127;
            dst[2 * ROWS] = ((u0.z + u1.z) + (u2.z + u3.z)) * inv127;
            dst[3 * ROWS] = ((u0.w + u1.w) + (u2.w + u3.w)) * inv127;
        }
    }
    __syncthreads();

    // --- GEMM1 mainloop: 96 k = 16 chunks of 6, ping-pong, zero barriers ---
    unsigned long long accp[8];
    #pragma unroll
    for (int j = 0; j < 8; j++) accp[j] = 0ull;

    const float2* wp = (const float2*)W1 + (size_t)(kg * KPER) * (H1 / 2) + c;
    const float*  vg = &vs[(kg * KPER) * ROWS];

    float2 wA[KCH], wB[KCH];
    #pragma unroll
    for (int u = 0; u < KCH; u++)
        wA[u] = __ldg(wp + u * (H1 / 2));
    wp += KCH * (H1 / 2);

    #pragma unroll 1
    for (int it = 0; it < NCH / 2; it++) {
        #pragma unroll
        for (int u = 0; u < KCH; u++)
            wB[u] = __ldg(wp + u * (H1 / 2));
        wp += KCH * (H1 / 2);
        {
            const float* vk = vg + (it * 2 * KCH) * ROWS;
            #pragma unroll
            for (int u = 0; u < KCH; u++)
                KSTEP2(wA[u], vk + u * ROWS);
        }
        if (it < NCH / 2 - 1) {
            #pragma unroll
            for (int u = 0; u < KCH; u++)
                wA[u] = __ldg(wp + u * (H1 / 2));
            wp += KCH * (H1 / 2);
        }
        {
            const float* vk = vg + (it * 2 * KCH + KCH) * ROWS;
            #pragma unroll
            for (int u = 0; u < KCH; u++)
                KSTEP2(wB[u], vk + u * ROWS);
        }
    }

    // --- Write 8 kgroup partials: h1p[kg][row*256 + 2c + {0,1}] ---
    __syncthreads();
    {
        float* hp = h1p + kg * (ROWS * H1);
        #pragma unroll
        for (int j = 0; j < 4; j++) {
            float lo0, hi0, lo1, hi1;
            asm("mov.b64 {%0, %1}, %2;" : "=f"(lo0), "=f"(hi0) : "l"(accp[j]));
            asm("mov.b64 {%0, %1}, %2;" : "=f"(lo1), "=f"(hi1) : "l"(accp[4 + j]));
            *(float2*)&hp[(2 * j) * H1 + 2 * c]     = make_float2(lo0, lo1);
            *(float2*)&hp[(2 * j + 1) * H1 + 2 * c] = make_float2(hi0, hi1);
        }
    }
    __syncthreads();

    // --- Reduce 8 partials -> h1s (bias + relu). 1024 threads x 2 floats ---
    {
        const int idx = tid * 2;           // 0..2046
        const int col = idx & (H1 - 1);
        float2 s = *(const float2*)&h1p[idx];
        #pragma unroll
        for (int g = 1; g < KGRPS; g++) {
            float2 p = *(const float2*)&h1p[g * (ROWS * H1) + idx];
            s.x += p.x; s.y += p.y;
        }
        float2 bb = *(const float2*)&b1[col];
        s.x = fmaxf(s.x + bb.x, 0.0f);
        s.y = fmaxf(s.y + bb.y, 0.0f);
        *(float2*)&h1s[idx] = s;
    }
    CP_WAIT(0);
    __syncthreads();

    // --- GEMM2 (smem): threads 0..511 -> (r = t>>6, j = t&63) ---
    if (tid < 512) {
        const int j = tid & (H2 - 1);
        const int r = tid >> 6;            // 0..7
        float s0 = 0.0f;
        #pragma unroll 16
        for (int k = 0; k < H1; k++)
            s0 = fmaf(h1s[r * H1 + k], sW2[k * H2 + j], s0);
        h2s[r * H2 + j] = fmaxf(s0 + __ldg(&b2[j]), 0.0f);
    }
    __syncthreads();

    // --- GEMM3: 16 outputs (8 rows x 2 logits) ---
    if (tid < ROWS * OUTC) {
        const int r = tid >> 1;
        const int j = tid & 1;
        float s = __ldg(&b3[j]);
        #pragma unroll 8
        for (int cc = 0; cc < H2; cc++)
            s = fmaf(h2s[r * H2 + cc], __ldg(&W3[cc * OUTC + j]), s);
        out[(size_t)(r0 + r) * OUTC + j] = s;
    }
}

// ---------------------------------------------------------------------------
extern "C" void kernel_launch(void* const* d_in, const int* in_sizes, int n_in,
                              void* d_out, int out_size) {
    const float* hidden = (const float*)d_in[0];
    const void*  mask   = d_in[1];
    const float* W1 = (const float*)d_in[2];
    const float* b1 = (const float*)d_in[3];
    const float* W2 = (const float*)d_in[4];
    const float* b2 = (const float*)d_in[5];
    const float* W3 = (const float*)d_in[6];
    const float* b3 = (const float*)d_in[7];
    float* out = (float*)d_out;

    static int smem_set = 0;
    if (!smem_set) {
        cudaFuncSetAttribute(mlp_kernel,
                             cudaFuncAttributeMaxDynamicSharedMemorySize,
                             SMEM_FLOATS * sizeof(float));
        smem_set = 1;
    }

    reduce_kernel<<<QTRS * BB, 192>>>(hidden, mask);
    mlp_kernel<<<BB / ROWS, 1024, SMEM_FLOATS * sizeof(float)>>>(
        W1, b1, W2, b2, W3, b3, out);
}

// round 16
// speedup vs baseline: 1.4444x; 1.0476x over previous
#include <cuda_runtime.h>
#include <cuda_bf16.h>

// Problem constants (SpectralClassifier: B=1024, S=128, D=768)
#define BB 1024
#define SS 128
#define DD 768
#define H1 256
#define H2 64
#define OUTC 2
#define ROWS 8
#define QTRS 4
#define DET_WORDS 256     // per-block detection sample (1KB, L2-broadcast)
#define KGRPS 8           // k-groups in MLP
#define KPER (DD / KGRPS) // 96 k per group
#define KCH 6             // k-steps per register chunk
#define NCH (KPER / KCH)  // 16 chunks

// Scratch (no cudaMalloc allowed).
__device__ float g_vp[QTRS * BB * DD];   // unscaled partial sums [quarter][b][d]

// packed dual-fp32 FMA (sm_100+)
#define FMA_F32X2(d, a, b, c) \
    asm("fma.rn.f32x2 %0, %1, %2, %3;" : "=l"(d) : "l"(a), "l"(b), "l"(c))

__device__ __forceinline__ void cpasync16(float* smem_dst, const float* gsrc) {
    unsigned saddr = (unsigned)__cvta_generic_to_shared(smem_dst);
    asm volatile("cp.async.cg.shared.global [%0], [%1], 16;" :: "r"(saddr), "l"(gsrc) : "memory");
}
#define CP_COMMIT()  asm volatile("cp.async.commit_group;" ::: "memory")
#define CP_WAIT(n)   asm volatile("cp.async.wait_group %0;" :: "n"(n) : "memory")

__device__ __forceinline__ bool mask_at(const void* mask, int idx, int mode) {
    if (mode == 0) return ((const int*)mask)[idx] != 0;
    if (mode == 1) return ((const float*)mask)[idx] != 0.0f;
    return ((const unsigned char*)mask)[idx] != 0;
}

// ---------------------------------------------------------------------------
// Kernel A: partial masked seq-sums with inline mask-dtype detection.
// 4096 blocks: blockIdx.x = b*4 + q. Register-capped (192,8) for 8 blocks/SM:
// higher occupancy -> more independent gather streams -> higher HBM%.
// ---------------------------------------------------------------------------
__global__ void __launch_bounds__(192, 8) reduce_kernel(
    const float* __restrict__ hidden, const void* __restrict__ mask)
{
    __shared__ int s_idx[32];
    __shared__ int s_cnt;
    __shared__ int s_mode;

    const int b   = blockIdx.x >> 2;
    const int q   = blockIdx.x & 3;
    const int lo  = (q == 0) ? 1 : (q * 32);
    const int nrows = (q == 0) ? 31 : 32;
    const int tid = threadIdx.x;

    {
        int bad_i = 0, bad_f = 0;
        const uint4* w4 = (const uint4*)mask;
        for (int i = tid; i < DET_WORDS / 4; i += 192) {
            uint4 v = __ldg(&w4[i]);
            unsigned arr[4] = {v.x, v.y, v.z, v.w};
            #pragma unroll
            for (int j = 0; j < 4; j++) {
                unsigned u = arr[j];
                if (u > 1u) bad_i = 1;
                float f = __uint_as_float(u);
                if (!(f == 0.0f || f == 1.0f)) bad_f = 1;
            }
        }
        bad_i = __any_sync(0xffffffffu, bad_i);
        bad_f = __any_sync(0xffffffffu, bad_f);
        if (tid == 0) s_mode = 0;
        __syncthreads();
        if ((tid & 31) == 0) {
            int mode = (!bad_i) ? 0 : ((!bad_f) ? 1 : 2);
            atomicMax(&s_mode, mode);
        }
        __syncthreads();
    }
    const int mode = s_mode;

    if (tid < 32) {
        bool m = (tid < nrows) && mask_at(mask, b * SS + lo + tid, mode);
        unsigned bal = __ballot_sync(0xffffffffu, m);
        if (m) s_idx[__popc(bal & ((1u << tid) - 1u))] = lo + tid;
        if (tid == 0) s_cnt = __popc(bal);
    }
    __syncthreads();

    const int cnt = s_cnt;
    const float4* hp = (const float4*)(hidden + (size_t)b * SS * DD);

    float4 a0 = make_float4(0.f, 0.f, 0.f, 0.f);
    float4 a1 = make_float4(0.f, 0.f, 0.f, 0.f);
    float4 a2 = make_float4(0.f, 0.f, 0.f, 0.f);
    float4 a3 = make_float4(0.f, 0.f, 0.f, 0.f);

    int i = 0;
    for (; i + 4 <= cnt; i += 4) {
        float4 x0 = __ldcs(&hp[s_idx[i]     * (DD / 4) + tid]);
        float4 x1 = __ldcs(&hp[s_idx[i + 1] * (DD / 4) + tid]);
        float4 x2 = __ldcs(&hp[s_idx[i + 2] * (DD / 4) + tid]);
        float4 x3 = __ldcs(&hp[s_idx[i + 3] * (DD / 4) + tid]);
        a0.x += x0.x; a0.y += x0.y; a0.z += x0.z; a0.w += x0.w;
        a1.x += x1.x; a1.y += x1.y; a1.z += x1.z; a1.w += x1.w;
        a2.x += x2.x; a2.y += x2.y; a2.z += x2.z; a2.w += x2.w;
        a3.x += x3.x; a3.y += x3.y; a3.z += x3.z; a3.w += x3.w;
    }
    for (; i < cnt; i++) {
        float4 x0 = __ldcs(&hp[s_idx[i] * (DD / 4) + tid]);
        a0.x += x0.x; a0.y += x0.y; a0.z += x0.z; a0.w += x0.w;
    }

    float4 r;
    r.x = (a0.x + a1.x) + (a2.x + a3.x);
    r.y = (a0.y + a1.y) + (a2.y + a3.y);
    r.z = (a0.z + a1.z) + (a2.z + a3.z);
    r.w = (a0.w + a1.w) + (a2.w + a3.w);
    ((float4*)(g_vp + (size_t)(q * BB + b) * DD))[tid] = r;
}

// ---------------------------------------------------------------------------
// Kernel B: full MLP per 8-row tile. 128 blocks x 1024 threads (32 warps/SM).
// W1 streamed LDG.64 -> registers (no smem echo), KCH=6 ping-pong, zero
// barriers in the mainloop. Thread: 2 cols x 8 rows x 96 k;
// kg = tid>>7 (8 kgroups), c = tid&127 (col pair 2c, 2c+1).  (R14 winner.)
// Dynamic smem (floats):
//   vs[DD*ROWS]        : 0     .. 6144
//   h1p[KGRPS][2048]   : 6144  .. 22528
//   h1s[ROWS*H1]       : 22528 .. 24576
//   sW2[H1*H2]         : 24576 .. 40960
//   h2s[ROWS*H2]       : 40960 .. 41472
// ---------------------------------------------------------------------------
#define SMEM_FLOATS 41472
#define OFF_VS   0
#define OFF_H1P  6144
#define OFF_H1S  22528
#define OFF_W2   24576
#define OFF_H2S  40960

// one k-step: w2v = float2 weights for 2 cols; vkp -> vs[k][0]
#define KSTEP2(w2v, vkp) do {                                             \
    unsigned long long w0, w1;                                            \
    asm("mov.b64 %0, {%1, %1};" : "=l"(w0) : "f"((w2v).x));               \
    asm("mov.b64 %0, {%1, %1};" : "=l"(w1) : "f"((w2v).y));               \
    const ulonglong2 va = *(const ulonglong2*)(vkp);                      \
    const ulonglong2 vb = *(const ulonglong2*)((vkp) + 4);                \
    FMA_F32X2(accp[0], va.x, w0, accp[0]);                                \
    FMA_F32X2(accp[1], va.y, w0, accp[1]);                                \
    FMA_F32X2(accp[2], vb.x, w0, accp[2]);                                \
    FMA_F32X2(accp[3], vb.y, w0, accp[3]);                                \
    FMA_F32X2(accp[4], va.x, w1, accp[4]);                                \
    FMA_F32X2(accp[5], va.y, w1, accp[5]);                                \
    FMA_F32X2(accp[6], vb.x, w1, accp[6]);                                \
    FMA_F32X2(accp[7], vb.y, w1, accp[7]);                                \
} while (0)

__global__ void __launch_bounds__(1024, 1) mlp_kernel(
    const float* __restrict__ W1, const float* __restrict__ b1,
    const float* __restrict__ W2, const float* __restrict__ b2,
    const float* __restrict__ W3, const float* __restrict__ b3,
    float* __restrict__ out)
{
    extern __shared__ float smf[];
    float* vs  = smf + OFF_VS;
    float* h1p = smf + OFF_H1P;
    float* h1s = smf + OFF_H1S;
    float* sW2 = smf + OFF_W2;
    float* h2s = smf + OFF_H2S;

    const int tid = threadIdx.x;
    const int c   = tid & 127;            // col pair: cols 2c, 2c+1
    const int kg  = tid >> 7;             // 0..7
    const int r0  = blockIdx.x * ROWS;
    const float inv127 = 1.0f / 127.0f;

    // --- Prologue: stage W2 via cp.async ---
    #pragma unroll
    for (int i = 0; i < H1 * H2 / 4; i += 1024)
        cpasync16(&sW2[(i + tid) * 4], &W2[(i + tid) * 4]);
    CP_COMMIT();

    // --- Stage v rows: v = (sum of 4 quarter partials)/127, layout [k][r] ---
    #pragma unroll
    for (int ii = 0; ii < 2; ii++) {
        int idx = ii * 1024 + tid;         // 0..2047, need < 1536
        if (idx < ROWS * (DD / 4)) {
            int r  = idx / (DD / 4);
            int c4 = idx % (DD / 4);
            const float4* p0 = (const float4*)(g_vp + (size_t)(0 * BB + r0 + r) * DD);
            const float4* p1 = (const float4*)(g_vp + (size_t)(1 * BB + r0 + r) * DD);
            const float4* p2 = (const float4*)(g_vp + (size_t)(2 * BB + r0 + r) * DD);
            const float4* p3 = (const float4*)(g_vp + (size_t)(3 * BB + r0 + r) * DD);
            float4 u0 = __ldg(&p0[c4]);
            float4 u1 = __ldg(&p1[c4]);
            float4 u2 = __ldg(&p2[c4]);
            float4 u3 = __ldg(&p3[c4]);
            float* dst = &vs[(c4 * 4) * ROWS + r];
            dst[0 * ROWS] = ((u0.x + u1.x) + (u2.x + u3.x)) * inv127;
            dst[1 * ROWS] = ((u0.y + u1.y) + (u2.y + u3.y)) * inv127;
            dst[2 * ROWS] = ((u0.z + u1.z) + (u2.z + u3.z)) * inv127;
            dst[3 * ROWS] = ((u0.w + u1.w) + (u2.w + u3.w)) * inv127;
        }
    }
    __syncthreads();

    // --- GEMM1 mainloop: 96 k = 16 chunks of 6, ping-pong, zero barriers ---
    unsigned long long accp[8];
    #pragma unroll
    for (int j = 0; j < 8; j++) accp[j] = 0ull;

    const float2* wp = (const float2*)W1 + (size_t)(kg * KPER) * (H1 / 2) + c;
    const float*  vg = &vs[(kg * KPER) * ROWS];

    float2 wA[KCH], wB[KCH];
    #pragma unroll
    for (int u = 0; u < KCH; u++)
        wA[u] = __ldg(wp + u * (H1 / 2));
    wp += KCH * (H1 / 2);

    #pragma unroll 1
    for (int it = 0; it < NCH / 2; it++) {
        #pragma unroll
        for (int u = 0; u < KCH; u++)
            wB[u] = __ldg(wp + u * (H1 / 2));
        wp += KCH * (H1 / 2);
        {
            const float* vk = vg + (it * 2 * KCH) * ROWS;
            #pragma unroll
            for (int u = 0; u < KCH; u++)
                KSTEP2(wA[u], vk + u * ROWS);
        }
        if (it < NCH / 2 - 1) {
            #pragma unroll
            for (int u = 0; u < KCH; u++)
                wA[u] = __ldg(wp + u * (H1 / 2));
            wp += KCH * (H1 / 2);
        }
        {
            const float* vk = vg + (it * 2 * KCH + KCH) * ROWS;
            #pragma unroll
            for (int u = 0; u < KCH; u++)
                KSTEP2(wB[u], vk + u * ROWS);
        }
    }

    // --- Write 8 kgroup partials: h1p[kg][row*256 + 2c + {0,1}] ---
    __syncthreads();
    {
        float* hp = h1p + kg * (ROWS * H1);
        #pragma unroll
        for (int j = 0; j < 4; j++) {
            float lo0, hi0, lo1, hi1;
            asm("mov.b64 {%0, %1}, %2;" : "=f"(lo0), "=f"(hi0) : "l"(accp[j]));
            asm("mov.b64 {%0, %1}, %2;" : "=f"(lo1), "=f"(hi1) : "l"(accp[4 + j]));
            *(float2*)&hp[(2 * j) * H1 + 2 * c]     = make_float2(lo0, lo1);
            *(float2*)&hp[(2 * j + 1) * H1 + 2 * c] = make_float2(hi0, hi1);
        }
    }
    __syncthreads();

    // --- Reduce 8 partials -> h1s (bias + relu). 1024 threads x 2 floats ---
    {
        const int idx = tid * 2;           // 0..2046
        const int col = idx & (H1 - 1);
        float2 s = *(const float2*)&h1p[idx];
        #pragma unroll
        for (int g = 1; g < KGRPS; g++) {
            float2 p = *(const float2*)&h1p[g * (ROWS * H1) + idx];
            s.x += p.x; s.y += p.y;
        }
        float2 bb = *(const float2*)&b1[col];
        s.x = fmaxf(s.x + bb.x, 0.0f);
        s.y = fmaxf(s.y + bb.y, 0.0f);
        *(float2*)&h1s[idx] = s;
    }
    CP_WAIT(0);
    __syncthreads();

    // --- GEMM2 (smem): threads 0..511 -> (r = t>>6, j = t&63) ---
    if (tid < 512) {
        const int j = tid & (H2 - 1);
        const int r = tid >> 6;            // 0..7
        float s0 = 0.0f;
        #pragma unroll 16
        for (int k = 0; k < H1; k++)
            s0 = fmaf(h1s[r * H1 + k], sW2[k * H2 + j], s0);
        h2s[r * H2 + j] = fmaxf(s0 + __ldg(&b2[j]), 0.0f);
    }
    __syncthreads();

    // --- GEMM3: 16 outputs (8 rows x 2 logits) ---
    if (tid < ROWS * OUTC) {
        const int r = tid >> 1;
        const int j = tid & 1;
        float s = __ldg(&b3[j]);
        #pragma unroll 8
        for (int cc = 0; cc < H2; cc++)
            s = fmaf(h2s[r * H2 + cc], __ldg(&W3[cc * OUTC + j]), s);
        out[(size_t)(r0 + r) * OUTC + j] = s;
    }
}

// ---------------------------------------------------------------------------
extern "C" void kernel_launch(void* const* d_in, const int* in_sizes, int n_in,
                              void* d_out, int out_size) {
    const float* hidden = (const float*)d_in[0];
    const void*  mask   = d_in[1];
    const float* W1 = (const float*)d_in[2];
    const float* b1 = (const float*)d_in[3];
    const float* W2 = (const float*)d_in[4];
    const float* b2 = (const float*)d_in[5];
    const float* W3 = (const float*)d_in[6];
    const float* b3 = (const float*)d_in[7];
    float* out = (float*)d_out;

    static int smem_set = 0;
    if (!smem_set) {
        cudaFuncSetAttribute(mlp_kernel,
                             cudaFuncAttributeMaxDynamicSharedMemorySize,
                             SMEM_FLOATS * sizeof(float));
        smem_set = 1;
    }

    reduce_kernel<<<QTRS * BB, 192>>>(hidden, mask);
    mlp_kernel<<<BB / ROWS, 1024, SMEM_FLOATS * sizeof(float)>>>(
        W1, b1, W2, b2, W3, b3, out);
}